// round 7
// baseline (speedup 1.0000x reference)
#include <cuda_runtime.h>
#include <math.h>

#define NNODES 172032
#define NGROUP 8192
#define FIN 171
#define FHID 256
#define FOUT 128

// ---------------- scratch (device globals; 16B-aligned) ----------------
__device__ __align__(16) float g_y1[(size_t)NNODES * FHID];
__device__ __align__(16) float g_W1t[FIN * FHID];    // [k][n]
__device__ __align__(16) float g_W2t[FHID * FOUT];   // [k][n]

// ---------------- packed f32x2 helpers (sm_100+) ----------------
__device__ __forceinline__ unsigned long long pack2(float x, float y) {
    unsigned long long r;
    asm("mov.b64 %0, {%1, %2};" : "=l"(r) : "f"(x), "f"(y));
    return r;
}
__device__ __forceinline__ float2 unpack2(unsigned long long v) {
    float2 r;
    asm("mov.b64 {%0, %1}, %2;" : "=f"(r.x), "=f"(r.y) : "l"(v));
    return r;
}
__device__ __forceinline__ unsigned long long ffma2(unsigned long long a,
                                                    unsigned long long b,
                                                    unsigned long long c) {
    unsigned long long d;
    asm("fma.rn.f32x2 %0, %1, %2, %3;" : "=l"(d) : "l"(a), "l"(b), "l"(c));
    return d;
}
__device__ __forceinline__ void cpa4(unsigned s, const float* g, int sz) {
    asm volatile("cp.async.ca.shared.global [%0], [%1], 4, %2;"
                 :: "r"(s), "l"(g), "r"(sz));
}
__device__ __forceinline__ void cpa16(unsigned s, const float* g, int sz) {
    asm volatile("cp.async.cg.shared.global [%0], [%1], 16, %2;"
                 :: "r"(s), "l"(g), "r"(sz));
}

// int32/int64 index reader (dtype detected at runtime)
__device__ __forceinline__ int rdidx(const void* p, long long i, bool w64) {
    return w64 ? (int)((const long long*)p)[i] : ((const int*)p)[i];
}

// ---------------- 0) transpose weights once ----------------
__global__ void transpose_w_kernel(const float* __restrict__ W1,
                                   const float* __restrict__ W2)
{
    int t = blockIdx.x * blockDim.x + threadIdx.x;
    if (t < FIN * FHID) {           // t = k*256 + n
        int k = t / FHID, n = t - k * FHID;
        g_W1t[t] = W1[n * FIN + k];
    }
    if (t < FHID * FOUT) {          // t = k*128 + n
        int k = t / FOUT, n = t - k * FOUT;
        g_W2t[t] = W2[n * FHID + k];
    }
}

// ---------------- 1) build x (writes directly into output x region) -------
__global__ void build_x_kernel(
    const float* __restrict__ x_in,
    const void* __restrict__ doc_id,
    const void* __restrict__ click,
    const void* __restrict__ query,
    const void* __restrict__ docu,
    const void* __restrict__ title,
    const float* __restrict__ qtab,
    const float* __restrict__ dtab,
    const float* __restrict__ ttab,
    const float* __restrict__ postab,
    const float* __restrict__ clktab,
    float* __restrict__ x_out)
{
    int t = blockIdx.x * blockDim.x + threadIdx.x;  // exact grid: N*171 threads
    bool w64 = (((const int*)doc_id)[1] == 0);
    int node = t / FIN;
    int col  = t - node * FIN;
    int g = node / 21;
    int r = node - g * 21;
    float v;
    if (r == 0) {
        if (col < 160) v = qtab[(size_t)rdidx(query, g, w64) * 160 + col];
        else           v = x_in[t];
    } else if (r <= 10) {
        int j = r - 1;
        if (col < 160)       v = dtab[(size_t)rdidx(docu, (long long)g * 10 + j, w64) * 160 + col];
        else if (col == 160) v = postab[j];
        else if (col == 161) v = clktab[rdidx(click, g, w64)];   // i == 0
        else                 v = x_in[t];
    } else {
        int j = r - 11;
        if (col < 160) v = ttab[(size_t)rdidx(title, (long long)g * 10 + j, w64) * 160 + col];
        else           v = x_in[t];
    }
    x_out[t] = v;
}

// src sets per dst within a 21-node group
__device__ __forceinline__ int get_srcs(int r, int* s) {
    if (r == 0) {
        s[0] = 0;
        for (int j = 0; j < 10; j++) s[1 + j] = 1 + j;
        return 11;
    }
    if (r <= 10) { s[0] = 0; s[1] = r; s[2] = r + 10; return 3; }
    s[0] = r - 10; s[1] = r; return 2;
}

// ---------------- fused GEMM + GAT aggregation -----------------
// LAYER 1: X[42,171] @ W1t -> h[42,256]; softmax-agg over 2 groups; y1=relu(+b1)
// LAYER 2: y1[84,256] @ W2t -> h[84,128]; agg over 4 groups; hs_out + sigmoid head
template <int LAYER>
__launch_bounds__(192, 3)
__global__ void fused_kernel(const float* __restrict__ Xg,
                             const float* __restrict__ avs,
                             const float* __restrict__ avd,
                             const float* __restrict__ bias,
                             const float* __restrict__ Wl,
                             const float* __restrict__ bl,
                             float* __restrict__ out0,   // hs_out (LAYER2)
                             float* __restrict__ y_out)  // y      (LAYER2)
{
    constexpr int K    = (LAYER == 1) ? FIN : FHID;
    constexpr int NOUT = (LAYER == 1) ? FHID : FOUT;
    constexpr int BM   = (LAYER == 1) ? 42 : 84;
    constexpr int NCT  = (LAYER == 1) ? 32 : 16;   // col-threads (8 cols each)
    constexpr int BK   = 16;
    constexpr int KT   = (K + BK - 1) / BK;
    constexpr int WP   = NOUT + 4;

    union __align__(16) SmemU {
        struct { float Xs[2][BM][BK]; float Ws[2][BK][WP]; } mm;
        float h[BM][NOUT];
    };
    __shared__ SmemU u;
    __shared__ float ss[BM], sd[BM];
    __shared__ float al[BM][11];

    const float* Wt = (LAYER == 1) ? g_W1t : g_W2t;
    const float* X  = (LAYER == 1) ? Xg : g_y1;
    float* outp     = (LAYER == 1) ? g_y1 : out0;   // device-side symbol ref

    const int tid = threadIdx.x;
    const int tc = tid & (NCT - 1);
    const int tr = tid / NCT;
    const int row0 = blockIdx.x * BM;
    const int c0 = tc * 8;

    const unsigned xs_base = (unsigned)__cvta_generic_to_shared(&u.mm.Xs[0][0][0]);
    const unsigned ws_base = (unsigned)__cvta_generic_to_shared(&u.mm.Ws[0][0][0]);
    constexpr unsigned XSZ = sizeof(float) * BM * BK;
    constexpr unsigned WSZ = sizeof(float) * BK * WP;

    unsigned long long acc[7][4];
#pragma unroll
    for (int i = 0; i < 7; i++)
#pragma unroll
        for (int j = 0; j < 4; j++) acc[i][j] = 0ull;

    auto load_tile = [&](int kt, int buf) {
        const int k0 = kt * BK;
        // A tile: [m][k] row-major, pitch 64B
        if (LAYER == 2) {
            // K=256: rows 16B-aligned, full tiles always valid
            for (int e = tid; e < BM * (BK / 4); e += 192) {
                int m = e >> 2, c = e & 3;
                cpa16(xs_base + buf * XSZ + (unsigned)(m * BK + c * 4) * 4,
                      X + (size_t)(row0 + m) * K + k0 + c * 4, 16);
            }
        } else {
            for (int e = tid; e < BM * BK; e += 192) {
                int m = e >> 4, k = e & 15;
                int gk = k0 + k;
                cpa4(xs_base + buf * XSZ + (unsigned)(m * BK + k) * 4,
                     X + (size_t)(row0 + m) * K + gk, gk < K ? 4 : 0);
            }
        }
        // W tile from transposed weights: 16B vectors
        for (int e = tid; e < BK * (NOUT / 4); e += 192) {
            int k = e / (NOUT / 4), n4 = e - k * (NOUT / 4);
            int gk = k0 + k;
            cpa16(ws_base + buf * WSZ + (unsigned)(k * WP + n4 * 4) * 4,
                  Wt + (size_t)gk * NOUT + n4 * 4,
                  (LAYER == 2 || gk < K) ? 16 : 0);
        }
        asm volatile("cp.async.commit_group;");
    };

    load_tile(0, 0);

    for (int kt = 0; kt < KT; ++kt) {
        const int buf = kt & 1;
        asm volatile("cp.async.wait_group 0;");
        __syncthreads();                    // tile kt visible; old buffer free
        if (kt + 1 < KT) load_tile(kt + 1, buf ^ 1);

#pragma unroll
        for (int k4 = 0; k4 < BK / 4; k4++) {
            float4 a4[7];
#pragma unroll
            for (int i = 0; i < 7; i++)
                a4[i] = *(const float4*)&u.mm.Xs[buf][tr * 7 + i][k4 * 4];
#pragma unroll
            for (int kk = 0; kk < 4; kk++) {
                const int k = k4 * 4 + kk;
                const ulonglong2 b01 = *(const ulonglong2*)&u.mm.Ws[buf][k][c0];
                const ulonglong2 b23 = *(const ulonglong2*)&u.mm.Ws[buf][k][c0 + 4];
                unsigned long long b[4] = {b01.x, b01.y, b23.x, b23.y};
                unsigned long long aa[7];
#pragma unroll
                for (int i = 0; i < 7; i++) {
                    const float av = (kk == 0) ? a4[i].x : (kk == 1) ? a4[i].y
                                   : (kk == 2) ? a4[i].z : a4[i].w;
                    aa[i] = pack2(av, av);
                }
#pragma unroll
                for (int i = 0; i < 7; i++)
#pragma unroll
                    for (int j = 0; j < 4; j++)
                        acc[i][j] = ffma2(aa[i], b[j], acc[i][j]);
            }
        }
    }
    __syncthreads();   // all warps done with mm buffers; union reuse safe

    // ---- epilogue part 1: store h to smem, fused s/d dots + shfl reduce
    float asv[8], adv[8];
#pragma unroll
    for (int j = 0; j < 8; j++) { asv[j] = avs[c0 + j]; adv[j] = avd[c0 + j]; }
#pragma unroll
    for (int i = 0; i < 7; i++) {
        const int lr = tr * 7 + i;
        float* hr = &u.h[lr][c0];
        ((ulonglong2*)hr)[0] = make_ulonglong2(acc[i][0], acc[i][1]);
        ((ulonglong2*)hr)[1] = make_ulonglong2(acc[i][2], acc[i][3]);
        float sp = 0.f, dp = 0.f;
#pragma unroll
        for (int j = 0; j < 4; j++) {
            float2 v = unpack2(acc[i][j]);
            sp += v.x * asv[2 * j] + v.y * asv[2 * j + 1];
            dp += v.x * adv[2 * j] + v.y * adv[2 * j + 1];
        }
#pragma unroll
        for (int o = NCT / 2; o >= 1; o >>= 1) {
            sp += __shfl_xor_sync(0xffffffffu, sp, o);
            dp += __shfl_xor_sync(0xffffffffu, dp, o);
        }
        if (tc == 0) { ss[lr] = sp; sd[lr] = dp; }
    }
    __syncthreads();

    // ---- part 2: softmax attention coefficients (one thread per dst row)
    if (tid < BM) {
        const int gi = tid / 21, r = tid - gi * 21;
        int s[11];
        const int ns = get_srcs(r, s);
        const float dv = sd[tid];
        float e[11], m = -1e30f;
        for (int k = 0; k < ns; k++) {
            float z = ss[gi * 21 + s[k]] + dv;
            z = (z > 0.f) ? z : 0.2f * z;    // leaky_relu 0.2
            e[k] = z;
            m = fmaxf(m, z);
        }
        float sum = 0.f;
        for (int k = 0; k < ns; k++) { e[k] = expf(e[k] - m); sum += e[k]; }
        float inv = 1.f / sum;
        for (int k = 0; k < ns; k++) al[tid][k] = e[k] * inv;
    }
    __syncthreads();

    // ---- part 3: aggregate + activation + outputs
    float bb[8];
#pragma unroll
    for (int j = 0; j < 8; j++) bb[j] = bias[c0 + j];
    float wlv[8];
    if (LAYER == 2) {
#pragma unroll
        for (int j = 0; j < 8; j++) wlv[j] = Wl[c0 + j];
    }
    const float bl0 = (LAYER == 2) ? bl[0] : 0.f;

#pragma unroll
    for (int i = 0; i < 7; i++) {
        const int lr = tr * 7 + i;
        const int gi = lr / 21, r = lr - gi * 21;
        int s[11];
        const int ns = get_srcs(r, s);
        float o[8];
#pragma unroll
        for (int j = 0; j < 8; j++) o[j] = bb[j];
        for (int k = 0; k < ns; k++) {
            const float w = al[lr][k];
            const float* hp = &u.h[gi * 21 + s[k]][c0];
            const float4 h0 = *(const float4*)hp;
            const float4 h1 = *(const float4*)(hp + 4);
            o[0] += w * h0.x; o[1] += w * h0.y; o[2] += w * h0.z; o[3] += w * h0.w;
            o[4] += w * h1.x; o[5] += w * h1.y; o[6] += w * h1.z; o[7] += w * h1.w;
        }
        const int row = row0 + lr;
        if (LAYER == 1) {
            float* yr = outp + (size_t)row * FHID + c0;
#pragma unroll
            for (int j = 0; j < 8; j++) o[j] = fmaxf(o[j], 0.f);
            ((float4*)yr)[0] = make_float4(o[0], o[1], o[2], o[3]);
            ((float4*)yr)[1] = make_float4(o[4], o[5], o[6], o[7]);
        } else {
            float* hr = outp + (size_t)row * FOUT + c0;
            ((float4*)hr)[0] = make_float4(o[0], o[1], o[2], o[3]);
            ((float4*)hr)[1] = make_float4(o[4], o[5], o[6], o[7]);
            float p = 0.f;
#pragma unroll
            for (int j = 0; j < 8; j++) p += fmaxf(o[j], 0.f) * wlv[j];
#pragma unroll
            for (int of = 8; of >= 1; of >>= 1)
                p += __shfl_xor_sync(0xffffffffu, p, of);
            if (tc == 0) y_out[row] = 1.f / (1.f + expf(-(p + bl0)));
        }
    }
}

// ---------------- launch ----------------
extern "C" void kernel_launch(void* const* d_in, const int* in_sizes, int n_in,
                              void* d_out, int out_size)
{
    const float* x_in   = (const float*)d_in[1];
    const void*  doc_id = d_in[3];
    const void*  click  = d_in[4];
    const void*  query  = d_in[5];
    const void*  docu   = d_in[6];
    const void*  title  = d_in[7];
    const float* qtab   = (const float*)d_in[8];
    const float* dtab   = (const float*)d_in[9];
    const float* ttab   = (const float*)d_in[10];
    const float* postab = (const float*)d_in[11];
    const float* clktab = (const float*)d_in[12];
    const float* W1  = (const float*)d_in[13];
    const float* as1 = (const float*)d_in[14];
    const float* ad1 = (const float*)d_in[15];
    const float* b1  = (const float*)d_in[16];
    const float* W2  = (const float*)d_in[17];
    const float* as2 = (const float*)d_in[18];
    const float* ad2 = (const float*)d_in[19];
    const float* b2  = (const float*)d_in[20];
    const float* Wl  = (const float*)d_in[21];
    const float* bl  = (const float*)d_in[22];

    float* out    = (float*)d_out;
    float* hs_out = out;                                   // [N,128]
    float* y_out  = out + (size_t)NNODES * FOUT;           // [N,1]
    float* x_out  = y_out + NNODES;                        // [N,171]

    transpose_w_kernel<<<(FIN * FHID + 255) / 256, 256>>>(W1, W2);

    build_x_kernel<<<(NNODES * FIN) / 256, 256>>>(
        x_in, doc_id, click, query, docu, title,
        qtab, dtab, ttab, postab, clktab, x_out);

    fused_kernel<1><<<NNODES / 42, 192>>>(x_out, as1, ad1, b1,
                                          nullptr, nullptr, nullptr, nullptr);

    fused_kernel<2><<<NNODES / 84, 192>>>(nullptr, as2, ad2, b2,
                                          Wl, bl, hs_out, y_out);
}

// round 8
// speedup vs baseline: 1.0426x; 1.0426x over previous
#include <cuda_runtime.h>
#include <math.h>

#define NNODES 172032
#define NGROUP 8192
#define FIN 171
#define FHID 256
#define FOUT 128

// ---------------- scratch (device globals; 16B-aligned) ----------------
__device__ __align__(16) float g_y1[(size_t)NNODES * FHID];
__device__ __align__(16) float g_W1t[FIN * FHID];    // [k][n]
__device__ __align__(16) float g_W2t[FHID * FOUT];   // [k][n]

// ---------------- packed f32x2 helpers (sm_100+) ----------------
__device__ __forceinline__ unsigned long long pack2(float x, float y) {
    unsigned long long r;
    asm("mov.b64 %0, {%1, %2};" : "=l"(r) : "f"(x), "f"(y));
    return r;
}
__device__ __forceinline__ float2 unpack2(unsigned long long v) {
    float2 r;
    asm("mov.b64 {%0, %1}, %2;" : "=f"(r.x), "=f"(r.y) : "l"(v));
    return r;
}
__device__ __forceinline__ unsigned long long ffma2(unsigned long long a,
                                                    unsigned long long b,
                                                    unsigned long long c) {
    unsigned long long d;
    asm("fma.rn.f32x2 %0, %1, %2, %3;" : "=l"(d) : "l"(a), "l"(b), "l"(c));
    return d;
}
__device__ __forceinline__ void cpa4(unsigned s, const float* g, int sz) {
    asm volatile("cp.async.ca.shared.global [%0], [%1], 4, %2;"
                 :: "r"(s), "l"(g), "r"(sz));
}
__device__ __forceinline__ void cpa16(unsigned s, const float* g, int sz) {
    asm volatile("cp.async.cg.shared.global [%0], [%1], 16, %2;"
                 :: "r"(s), "l"(g), "r"(sz));
}

// int32/int64 index reader (dtype detected at runtime)
__device__ __forceinline__ int rdidx(const void* p, long long i, bool w64) {
    return w64 ? (int)((const long long*)p)[i] : ((const int*)p)[i];
}

// ---------------- 0) transpose weights once ----------------
__global__ void transpose_w_kernel(const float* __restrict__ W1,
                                   const float* __restrict__ W2)
{
    int t = blockIdx.x * blockDim.x + threadIdx.x;
    if (t < FIN * FHID) {           // t = k*256 + n
        int k = t / FHID, n = t - k * FHID;
        g_W1t[t] = W1[n * FIN + k];
    }
    if (t < FHID * FOUT) {          // t = k*128 + n
        int k = t / FOUT, n = t - k * FOUT;
        g_W2t[t] = W2[n * FHID + k];
    }
}

// ---------------- 1) build x (writes directly into output x region) -------
__global__ void build_x_kernel(
    const float* __restrict__ x_in,
    const void* __restrict__ doc_id,
    const void* __restrict__ click,
    const void* __restrict__ query,
    const void* __restrict__ docu,
    const void* __restrict__ title,
    const float* __restrict__ qtab,
    const float* __restrict__ dtab,
    const float* __restrict__ ttab,
    const float* __restrict__ postab,
    const float* __restrict__ clktab,
    float* __restrict__ x_out)
{
    int t = blockIdx.x * blockDim.x + threadIdx.x;  // exact grid: N*171 threads
    bool w64 = (((const int*)doc_id)[1] == 0);
    int node = t / FIN;
    int col  = t - node * FIN;
    int g = node / 21;
    int r = node - g * 21;
    float v;
    if (r == 0) {
        if (col < 160) v = qtab[(size_t)rdidx(query, g, w64) * 160 + col];
        else           v = x_in[t];
    } else if (r <= 10) {
        int j = r - 1;
        if (col < 160)       v = dtab[(size_t)rdidx(docu, (long long)g * 10 + j, w64) * 160 + col];
        else if (col == 160) v = postab[j];
        else if (col == 161) v = clktab[rdidx(click, g, w64)];   // i == 0
        else                 v = x_in[t];
    } else {
        int j = r - 11;
        if (col < 160) v = ttab[(size_t)rdidx(title, (long long)g * 10 + j, w64) * 160 + col];
        else           v = x_in[t];
    }
    x_out[t] = v;
}

// src sets per dst within a 21-node group
__device__ __forceinline__ int get_srcs(int r, int* s) {
    if (r == 0) {
        s[0] = 0;
        for (int j = 0; j < 10; j++) s[1 + j] = 1 + j;
        return 11;
    }
    if (r <= 10) { s[0] = 0; s[1] = r; s[2] = r + 10; return 3; }
    s[0] = r - 10; s[1] = r; return 2;
}

// ---------------- fused GEMM + GAT aggregation -----------------
// LAYER 1: X[42,171] @ W1t -> h[42,256]; softmax-agg over 2 groups; y1=relu(+b1)
// LAYER 2: y1[84,256] @ W2t -> h[84,128]; agg over 4 groups; hs_out + sigmoid head
template <int LAYER>
__launch_bounds__(192, 3)
__global__ void fused_kernel(const float* __restrict__ Xg,
                             const float* __restrict__ avs,
                             const float* __restrict__ avd,
                             const float* __restrict__ bias,
                             const float* __restrict__ Wl,
                             const float* __restrict__ bl,
                             float* __restrict__ out0,   // hs_out (LAYER2)
                             float* __restrict__ y_out)  // y      (LAYER2)
{
    constexpr int K    = (LAYER == 1) ? FIN : FHID;
    constexpr int NOUT = (LAYER == 1) ? FHID : FOUT;
    constexpr int BM   = (LAYER == 1) ? 42 : 84;
    constexpr int NCT  = (LAYER == 1) ? 32 : 16;   // col-threads (8 cols each)
    constexpr int NRT  = BM / 7;                   // row-threads (7 rows each)
    constexpr int BK   = (LAYER == 1) ? 16 : 32;
    constexpr int KT   = (K + BK - 1) / BK;        // 11 / 8
    constexpr int SLOTS = NRT * 8;                 // padded A slots
    constexpr int XP   = SLOTS + 4;
    constexpr int WP   = NOUT + 4;

    union __align__(16) SmemU {
        struct { float Xs[2][BK][XP]; float Ws[2][BK][WP]; } mm;
        float h[BM][NOUT];
    };
    __shared__ SmemU u;
    __shared__ float ss[BM], sd[BM];
    __shared__ float al[BM][11];

    const float* Wt = (LAYER == 1) ? g_W1t : g_W2t;
    const float* X  = (LAYER == 1) ? Xg : g_y1;
    float* outp     = (LAYER == 1) ? g_y1 : out0;   // device-side symbol ref

    const int tid = threadIdx.x;
    const int tc = tid & (NCT - 1);
    const int tr = tid / NCT;
    const int row0 = blockIdx.x * BM;
    const int c0 = tc * 8;

    const unsigned xs_base = (unsigned)__cvta_generic_to_shared(&u.mm.Xs[0][0][0]);
    const unsigned ws_base = (unsigned)__cvta_generic_to_shared(&u.mm.Ws[0][0][0]);
    constexpr unsigned XSZ = sizeof(float) * BK * XP;
    constexpr unsigned WSZ = sizeof(float) * BK * WP;

    unsigned long long acc[7][4];
#pragma unroll
    for (int i = 0; i < 7; i++)
#pragma unroll
        for (int j = 0; j < 4; j++) acc[i][j] = 0ull;

    auto load_tile = [&](int kt, int buf) {
        const int k0 = kt * BK;
        // A tile: [k][slot] layout, slot = (m/7)*8 + m%7
        for (int e = tid; e < BM * BK; e += 192) {
            int m = e / BK, k = e - m * BK;
            int q7 = m / 7;
            int slot = q7 * 8 + (m - q7 * 7);
            int gk = k0 + k;
            cpa4(xs_base + buf * XSZ + (unsigned)(k * XP + slot) * 4,
                 X + (size_t)(row0 + m) * K + gk,
                 (LAYER == 2 || gk < K) ? 4 : 0);
        }
        // W tile from transposed weights: 16B vectors
        for (int e = tid; e < BK * (NOUT / 4); e += 192) {
            int k = e / (NOUT / 4), n4 = e - k * (NOUT / 4);
            int gk = k0 + k;
            cpa16(ws_base + buf * WSZ + (unsigned)(k * WP + n4 * 4) * 4,
                  Wt + (size_t)gk * NOUT + n4 * 4,
                  (LAYER == 2 || gk < K) ? 16 : 0);
        }
        asm volatile("cp.async.commit_group;");
    };

    load_tile(0, 0);

    for (int kt = 0; kt < KT; ++kt) {
        const int buf = kt & 1;
        asm volatile("cp.async.wait_group 0;");
        __syncthreads();                 // tile kt visible; prev compute done
        if (kt + 1 < KT) load_tile(kt + 1, buf ^ 1);

#pragma unroll
        for (int k = 0; k < BK; k++) {
            const float4 a0 = *(const float4*)&u.mm.Xs[buf][k][tr * 8];
            const float4 a1 = *(const float4*)&u.mm.Xs[buf][k][tr * 8 + 4];
            const ulonglong2 b01 = *(const ulonglong2*)&u.mm.Ws[buf][k][c0];
            const ulonglong2 b23 = *(const ulonglong2*)&u.mm.Ws[buf][k][c0 + 4];
            unsigned long long b[4] = {b01.x, b01.y, b23.x, b23.y};
            unsigned long long aa[7];
            aa[0] = pack2(a0.x, a0.x); aa[1] = pack2(a0.y, a0.y);
            aa[2] = pack2(a0.z, a0.z); aa[3] = pack2(a0.w, a0.w);
            aa[4] = pack2(a1.x, a1.x); aa[5] = pack2(a1.y, a1.y);
            aa[6] = pack2(a1.z, a1.z);
#pragma unroll
            for (int i = 0; i < 7; i++)
#pragma unroll
                for (int j = 0; j < 4; j++)
                    acc[i][j] = ffma2(aa[i], b[j], acc[i][j]);
        }
    }
    __syncthreads();   // all warps done with mm buffers; union reuse safe

    // ---- epilogue part 1: store h to smem, fused s/d dots + shfl reduce
    float asv[8], adv[8];
#pragma unroll
    for (int j = 0; j < 8; j++) { asv[j] = avs[c0 + j]; adv[j] = avd[c0 + j]; }
#pragma unroll
    for (int i = 0; i < 7; i++) {
        const int lr = tr * 7 + i;
        float* hr = &u.h[lr][c0];
        ((ulonglong2*)hr)[0] = make_ulonglong2(acc[i][0], acc[i][1]);
        ((ulonglong2*)hr)[1] = make_ulonglong2(acc[i][2], acc[i][3]);
        float sp = 0.f, dp = 0.f;
#pragma unroll
        for (int j = 0; j < 4; j++) {
            float2 v = unpack2(acc[i][j]);
            sp += v.x * asv[2 * j] + v.y * asv[2 * j + 1];
            dp += v.x * adv[2 * j] + v.y * adv[2 * j + 1];
        }
#pragma unroll
        for (int o = NCT / 2; o >= 1; o >>= 1) {
            sp += __shfl_xor_sync(0xffffffffu, sp, o);
            dp += __shfl_xor_sync(0xffffffffu, dp, o);
        }
        if (tc == 0) { ss[lr] = sp; sd[lr] = dp; }
    }
    __syncthreads();

    // ---- part 2: softmax attention coefficients (one thread per dst row)
    if (tid < BM) {
        const int gi = tid / 21, r = tid - gi * 21;
        int s[11];
        const int ns = get_srcs(r, s);
        const float dv = sd[tid];
        float e[11], m = -1e30f;
        for (int k = 0; k < ns; k++) {
            float z = ss[gi * 21 + s[k]] + dv;
            z = (z > 0.f) ? z : 0.2f * z;    // leaky_relu 0.2
            e[k] = z;
            m = fmaxf(m, z);
        }
        float sum = 0.f;
        for (int k = 0; k < ns; k++) { e[k] = expf(e[k] - m); sum += e[k]; }
        float inv = 1.f / sum;
        for (int k = 0; k < ns; k++) al[tid][k] = e[k] * inv;
    }
    __syncthreads();

    // ---- part 3: aggregate + activation + outputs
    float bb[8];
#pragma unroll
    for (int j = 0; j < 8; j++) bb[j] = bias[c0 + j];
    float wlv[8];
    if (LAYER == 2) {
#pragma unroll
        for (int j = 0; j < 8; j++) wlv[j] = Wl[c0 + j];
    }
    const float bl0 = (LAYER == 2) ? bl[0] : 0.f;

#pragma unroll
    for (int i = 0; i < 7; i++) {
        const int lr = tr * 7 + i;
        const int gi = lr / 21, r = lr - gi * 21;
        int s[11];
        const int ns = get_srcs(r, s);
        float o[8];
#pragma unroll
        for (int j = 0; j < 8; j++) o[j] = bb[j];
        for (int k = 0; k < ns; k++) {
            const float w = al[lr][k];
            const float* hp = &u.h[gi * 21 + s[k]][c0];
            const float4 h0 = *(const float4*)hp;
            const float4 h1 = *(const float4*)(hp + 4);
            o[0] += w * h0.x; o[1] += w * h0.y; o[2] += w * h0.z; o[3] += w * h0.w;
            o[4] += w * h1.x; o[5] += w * h1.y; o[6] += w * h1.z; o[7] += w * h1.w;
        }
        const int row = row0 + lr;
        if (LAYER == 1) {
            float* yr = outp + (size_t)row * FHID + c0;
#pragma unroll
            for (int j = 0; j < 8; j++) o[j] = fmaxf(o[j], 0.f);
            ((float4*)yr)[0] = make_float4(o[0], o[1], o[2], o[3]);
            ((float4*)yr)[1] = make_float4(o[4], o[5], o[6], o[7]);
        } else {
            float* hr = outp + (size_t)row * FOUT + c0;
            ((float4*)hr)[0] = make_float4(o[0], o[1], o[2], o[3]);
            ((float4*)hr)[1] = make_float4(o[4], o[5], o[6], o[7]);
            float p = 0.f;
#pragma unroll
            for (int j = 0; j < 8; j++) p += fmaxf(o[j], 0.f) * wlv[j];
#pragma unroll
            for (int of = 8; of >= 1; of >>= 1)
                p += __shfl_xor_sync(0xffffffffu, p, of);
            if (tc == 0) y_out[row] = 1.f / (1.f + expf(-(p + bl0)));
        }
    }
}

// ---------------- launch ----------------
extern "C" void kernel_launch(void* const* d_in, const int* in_sizes, int n_in,
                              void* d_out, int out_size)
{
    const float* x_in   = (const float*)d_in[1];
    const void*  doc_id = d_in[3];
    const void*  click  = d_in[4];
    const void*  query  = d_in[5];
    const void*  docu   = d_in[6];
    const void*  title  = d_in[7];
    const float* qtab   = (const float*)d_in[8];
    const float* dtab   = (const float*)d_in[9];
    const float* ttab   = (const float*)d_in[10];
    const float* postab = (const float*)d_in[11];
    const float* clktab = (const float*)d_in[12];
    const float* W1  = (const float*)d_in[13];
    const float* as1 = (const float*)d_in[14];
    const float* ad1 = (const float*)d_in[15];
    const float* b1  = (const float*)d_in[16];
    const float* W2  = (const float*)d_in[17];
    const float* as2 = (const float*)d_in[18];
    const float* ad2 = (const float*)d_in[19];
    const float* b2  = (const float*)d_in[20];
    const float* Wl  = (const float*)d_in[21];
    const float* bl  = (const float*)d_in[22];

    float* out    = (float*)d_out;
    float* hs_out = out;                                   // [N,128]
    float* y_out  = out + (size_t)NNODES * FOUT;           // [N,1]
    float* x_out  = y_out + NNODES;                        // [N,171]

    transpose_w_kernel<<<(FIN * FHID + 255) / 256, 256>>>(W1, W2);

    build_x_kernel<<<(NNODES * FIN) / 256, 256>>>(
        x_in, doc_id, click, query, docu, title,
        qtab, dtab, ttab, postab, clktab, x_out);

    fused_kernel<1><<<NNODES / 42, 192>>>(x_out, as1, ad1, b1,
                                          nullptr, nullptr, nullptr, nullptr);

    fused_kernel<2><<<NNODES / 84, 192>>>(nullptr, as2, ad2, b2,
                                          Wl, bl, hs_out, y_out);
}